// round 12
// baseline (speedup 1.0000x reference)
#include <cuda_runtime.h>
#include <cuda_fp16.h>
#include <cstdint>

// ----------------------------------------------------------------------------
// SelfAttention: out = Attn(x @ Wqkv) @ Wout, causal, H=16, Kd=64
// B=4, L=2048, D=1024 -> tokens = 8192
// R12: GEMM -> 128x256 block tile, 64x64 warp tile (128B LDS per MMA, was 384),
//      1 CTA/SM, 3-stage pipeline, persistent. Attention unchanged (R11).
// ----------------------------------------------------------------------------

#define TOKENS 8192
#define LSEQ   2048
#define DMODEL 1024
#define HEADS  16
#define KD     64
#define BH_CNT (4 * HEADS)   // 64
#define PERSIST_CTAS 152     // 1 per SM

// ---------------- scratch ----------------------------------------------------
__device__ __half g_x16[(size_t)TOKENS * DMODEL];
__device__ __half g_wqkvT[(size_t)3 * DMODEL * DMODEL];
__device__ __half g_woutT[(size_t)DMODEL * DMODEL];
__device__ __half g_q16[(size_t)BH_CNT * LSEQ * KD];
__device__ __half g_k16[(size_t)BH_CNT * LSEQ * KD];
__device__ __half g_v16[(size_t)BH_CNT * LSEQ * KD];
__device__ __half g_att16[(size_t)TOKENS * DMODEL];

// ---------------- helpers ----------------------------------------------------
__device__ __forceinline__ uint32_t smem_u32(const void* p) {
    uint32_t a;
    asm("{ .reg .u64 t; cvta.to.shared.u64 t, %1; cvt.u32.u64 %0, t; }" : "=r"(a) : "l"(p));
    return a;
}
__device__ __forceinline__ void cp16(uint32_t s, const void* g) {
    asm volatile("cp.async.cg.shared.global [%0], [%1], 16;" :: "r"(s), "l"(g));
}
#define CP_COMMIT() asm volatile("cp.async.commit_group;" ::: "memory")
#define CP_WAIT0()  asm volatile("cp.async.wait_group 0;" ::: "memory")
#define CP_WAIT1()  asm volatile("cp.async.wait_group 1;" ::: "memory")

__device__ __forceinline__ void ldsm4(uint32_t* r, uint32_t addr) {
    asm volatile("ldmatrix.sync.aligned.m8n8.x4.shared.b16 {%0,%1,%2,%3}, [%4];"
                 : "=r"(r[0]), "=r"(r[1]), "=r"(r[2]), "=r"(r[3]) : "r"(addr));
}
__device__ __forceinline__ void ldsm4t(uint32_t* r, uint32_t addr) {
    asm volatile("ldmatrix.sync.aligned.m8n8.x4.trans.shared.b16 {%0,%1,%2,%3}, [%4];"
                 : "=r"(r[0]), "=r"(r[1]), "=r"(r[2]), "=r"(r[3]) : "r"(addr));
}
__device__ __forceinline__ void mma16816(float* c, const uint32_t* a, const uint32_t* b) {
    asm volatile("mma.sync.aligned.m16n8k16.row.col.f32.f16.f16.f32 "
                 "{%0,%1,%2,%3}, {%4,%5,%6,%7}, {%8,%9}, {%0,%1,%2,%3};"
                 : "+f"(c[0]), "+f"(c[1]), "+f"(c[2]), "+f"(c[3])
                 : "r"(a[0]), "r"(a[1]), "r"(a[2]), "r"(a[3]), "r"(b[0]), "r"(b[1]));
}
__device__ __forceinline__ float ex2(float x) {
    float y;
    asm("ex2.approx.f32 %0, %1;" : "=f"(y) : "f"(x));
    return y;
}
__device__ __forceinline__ unsigned short h16(float v) {
    return __half_as_ushort(__float2half_rn(v));
}
__device__ __forceinline__ uint32_t pack2(unsigned short a, unsigned short b) {
    return (uint32_t)a | ((uint32_t)b << 16);
}

// ---------------------------------------------------------------------------
// Prep kernels
// ---------------------------------------------------------------------------
__global__ void convert_f16_kernel(const float* __restrict__ in,
                                   __half* __restrict__ o16, int n4) {
    int i = blockIdx.x * blockDim.x + threadIdx.x;
    if (i >= n4) return;
    float4 v = ((const float4*)in)[i];
    ((ushort4*)o16)[i] = make_ushort4(h16(v.x), h16(v.y), h16(v.z), h16(v.w));
}

__global__ void transpose_f16_kernel(const float* __restrict__ W,
                                     __half* __restrict__ T16,
                                     int K, int N) {
    __shared__ float t[32][33];
    int n0 = blockIdx.x * 32, k0 = blockIdx.y * 32;
    int tx = threadIdx.x, ty = threadIdx.y;
#pragma unroll
    for (int j = 0; j < 4; j++) {
        int k = ty + j * 8;
        t[k][tx] = W[(size_t)(k0 + k) * N + n0 + tx];
    }
    __syncthreads();
#pragma unroll
    for (int j = 0; j < 4; j++) {
        int nl = ty + j * 8;
        T16[(size_t)(n0 + nl) * K + k0 + tx] = __ushort_as_half(h16(t[tx][nl]));
    }
}

// ---------------------------------------------------------------------------
// Persistent HMMA GEMM, pure fp16: C = A * B^T. 128x256 block tile, 64x64
// warp tile, BK=64, 8 warps, 3-stage cp.async pipeline, 1 CTA/SM.
// MODE 0: C fp32.  MODE 1: head-major fp16 q/k/v epilogue (q scaled).
// ---------------------------------------------------------------------------
#define BM 128
#define BN 256
#define BK 64
#define RSTRIDE 144                    // 128B data + 16B pad
#define TILE_A  (128 * RSTRIDE)        // 18432
#define TILE_BB (256 * RSTRIDE)        // 36864
#define OFF_A   0
#define OFF_B   TILE_A
#define STAGE_B (TILE_A + TILE_BB)     // 55296
#define GEMM_SMEM (3 * STAGE_B)        // 165888
// Q scale: 1/sqrt(64) * log2(e)  (softmax runs in exp2 domain)
#define QSCALE (0.125f * 1.4426950408889634f)

template <int MODE>
__global__ __launch_bounds__(256, 1) void gemm_mma_kernel(
    const __half* __restrict__ A, const __half* __restrict__ B,
    float* __restrict__ C,
    __half* __restrict__ q16, __half* __restrict__ k16, __half* __restrict__ v16,
    int M, int N, int K) {
    extern __shared__ __align__(128) char smem[];
    const uint32_t sb = smem_u32(smem);
    const int tid  = threadIdx.x;
    const int lane = tid & 31;
    const int wid  = tid >> 5;
    const int wm = (wid & 1) * 64;          // 2 m-groups
    const int wn = (wid >> 1) * 64;         // 4 n-groups of 64 cols
    const int NS = K / BK;                  // 16
    const int nmt = M / BM;
    const int ntiles = nmt * (N / BN);

    const uint32_t a_off = (uint32_t)((lane & 15) * RSTRIDE + (lane >> 4) * 16);
    const uint32_t b_off = (uint32_t)((((lane >> 4) & 1) * 8 + (lane & 7)) * RSTRIDE +
                                      ((lane >> 3) & 1) * 16);

    for (int t = blockIdx.x; t < ntiles; t += gridDim.x) {
        const int m0 = (t % nmt) * BM;
        const int n0 = (t / nmt) * BN;

        float acc[4][8][4];
#pragma unroll
        for (int i = 0; i < 4; i++)
#pragma unroll
            for (int j = 0; j < 8; j++)
#pragma unroll
                for (int q = 0; q < 4; q++) acc[i][j][q] = 0.0f;

        auto load_stage = [&](int s) {
            const uint32_t base = sb + (uint32_t)(s % 3) * STAGE_B;
            const int k0 = s * BK;
            // A: 128 rows x 8 chunks = 1024 -> 4/thread
            for (int i = tid; i < 1024; i += 256) {
                int row = i >> 3;
                int ch  = (i & 7) * 16;
                uint32_t so = (uint32_t)(row * RSTRIDE + ch);
                cp16(base + OFF_A + so, A + (size_t)(m0 + row) * K + k0 + (ch >> 1));
            }
            // B: 256 rows x 8 chunks = 2048 -> 8/thread
            for (int i = tid; i < 2048; i += 256) {
                int row = i >> 3;
                int ch  = (i & 7) * 16;
                uint32_t so = (uint32_t)(row * RSTRIDE + ch);
                cp16(base + OFF_B + so, B + (size_t)(n0 + row) * K + k0 + (ch >> 1));
            }
            CP_COMMIT();
        };

        load_stage(0);
        load_stage(1);

        for (int s = 0; s < NS; s++) {
            if (s + 1 < NS) { CP_WAIT1(); }
            else            { CP_WAIT0(); }
            __syncthreads();
            if (s + 2 < NS) load_stage(s + 2);

            const uint32_t base = sb + (uint32_t)(s % 3) * STAGE_B;
#pragma unroll
            for (int kk = 0; kk < 4; kk++) {
                const uint32_t koff = kk * 32;
                uint32_t af[4][4], bf[4][4];
#pragma unroll
                for (int mt = 0; mt < 4; mt++) {
                    uint32_t r = base + (uint32_t)((wm + mt * 16) * RSTRIDE) + koff;
                    ldsm4(af[mt], r + OFF_A + a_off);
                }
#pragma unroll
                for (int ng = 0; ng < 4; ng++) {
                    uint32_t r = base + (uint32_t)((wn + ng * 16) * RSTRIDE) + koff;
                    ldsm4(bf[ng], r + OFF_B + b_off);
                }
#pragma unroll
                for (int mt = 0; mt < 4; mt++)
#pragma unroll
                    for (int nt = 0; nt < 8; nt++)
                        mma16816(acc[mt][nt], af[mt], &bf[nt >> 1][(nt & 1) * 2]);
            }
        }

        if (MODE == 0) {
#pragma unroll
            for (int mt = 0; mt < 4; mt++)
#pragma unroll
                for (int nt = 0; nt < 8; nt++) {
                    int row = m0 + wm + mt * 16 + (lane >> 2);
                    int col = n0 + wn + nt * 8 + (lane & 3) * 2;
                    *(float2*)&C[(size_t)row * N + col] =
                        make_float2(acc[mt][nt][0], acc[mt][nt][1]);
                    *(float2*)&C[(size_t)(row + 8) * N + col] =
                        make_float2(acc[mt][nt][2], acc[mt][nt][3]);
                }
        } else {
            const int sec = (n0 + wn) >> 10;          // 0=q 1=k 2=v
            const int hh  = ((n0 + wn) >> 6) & 15;
            __half* DST = (sec == 0) ? q16 : (sec == 1) ? k16 : v16;
            const float scl = (sec == 0) ? QSCALE : 1.0f;
#pragma unroll
            for (int mt = 0; mt < 4; mt++)
#pragma unroll
                for (int nt = 0; nt < 8; nt++) {
                    int row = m0 + wm + mt * 16 + (lane >> 2);
                    int d   = nt * 8 + (lane & 3) * 2;    // wn multiple of 64
                    int b   = row >> 11;
                    int ll  = row & 2047;
                    size_t idx = ((size_t)(b * HEADS + hh) * LSEQ + ll) * KD + d;
                    *(uint32_t*)(DST + idx) =
                        pack2(h16(acc[mt][nt][0] * scl), h16(acc[mt][nt][1] * scl));
                    *(uint32_t*)(DST + idx + (size_t)8 * KD) =
                        pack2(h16(acc[mt][nt][2] * scl), h16(acc[mt][nt][3] * scl));
                }
        }
        __syncthreads();   // all frag reads done before next tile's loads
    }
}

// ---------------------------------------------------------------------------
// Flash attention, pure fp16 MMA, causal, exp2 softmax (Q pre-scaled by
// log2(e)/8). 128-row kv stages, 2 CTA/SM, heavy q-tiles first. (R11)
// ---------------------------------------------------------------------------
#define ASTRIDE 144
#define AQ_OFF  0
#define ASTG0   (128 * ASTRIDE)        // 18432 (Q tile)
#define ASTG_SZ (2 * 128 * ASTRIDE)    // 36864 per stage (K, V: 128 rows each)
#define AK 0
#define AV (128 * ASTRIDE)
#define ATT_SMEM (ASTG0 + 2 * ASTG_SZ) // 92160

__global__ __launch_bounds__(256, 2) void attn_mma_kernel(
    const __half* __restrict__ q16,
    const __half* __restrict__ k16, const __half* __restrict__ v16,
    __half* __restrict__ att16) {
    extern __shared__ __align__(128) char smem[];
    const uint32_t sb = smem_u32(smem);
    const int tid  = threadIdx.x;
    const int lane = tid & 31;
    const int wid  = tid >> 5;
    const int qt   = gridDim.x - 1 - blockIdx.x;   // heavy tiles first
    const int bh   = blockIdx.y;
    const int q0   = qt * 128;
    const int nst  = qt + 1;

    const size_t hb = (size_t)bh * LSEQ * KD;
    const char* Qp = (const char*)(q16 + hb + (size_t)q0 * KD);
    const char* Kp = (const char*)(k16 + hb);
    const char* Vp = (const char*)(v16 + hb);

    auto load_q = [&]() {
        for (int i = tid; i < 1024; i += 256) {
            int row = i >> 3, ch = (i & 7) * 16;
            uint32_t so = (uint32_t)(row * ASTRIDE + ch);
            cp16(sb + AQ_OFF + so, Qp + (size_t)row * 128 + ch);
        }
    };
    auto load_stage = [&](int st) {
        const uint32_t base = sb + ASTG0 + (uint32_t)(st & 1) * ASTG_SZ;
        for (int i = tid; i < 1024; i += 256) {
            int row = i >> 3, ch = (i & 7) * 16;
            uint32_t so = (uint32_t)(row * ASTRIDE + ch);
            size_t go = (size_t)(st * 128 + row) * 128 + ch;
            cp16(base + AK + so, Kp + go);
            cp16(base + AV + so, Vp + go);
        }
        CP_COMMIT();
    };

    load_q();
    load_stage(0);

    const uint32_t a_off = (uint32_t)((lane & 15) * ASTRIDE + (lane >> 4) * 16);
    const uint32_t b_off = (uint32_t)((((lane >> 4) & 1) * 8 + (lane & 7)) * ASTRIDE +
                                      ((lane >> 3) & 1) * 16);
    const uint32_t v_off = (uint32_t)((lane & 15) * ASTRIDE + (lane >> 4) * 16);

    uint32_t qf[4][4];
    float oacc[8][4];
#pragma unroll
    for (int i = 0; i < 8; i++)
#pragma unroll
        for (int j = 0; j < 4; j++) oacc[i][j] = 0.0f;
    float mr0 = -1e30f, mr1 = -1e30f, lr0 = 0.0f, lr1 = 0.0f;

    const int r0 = q0 + wid * 16 + (lane >> 2);
    const int r1 = r0 + 8;

    for (int st = 0; st < nst; st++) {
        CP_WAIT0();
        __syncthreads();
        if (st + 1 < nst) load_stage(st + 1);

        if (st == 0) {
#pragma unroll
            for (int kc = 0; kc < 4; kc++) {
                uint32_t r = sb + (uint32_t)(wid * 16 * ASTRIDE) + kc * 32 + a_off;
                ldsm4(qf[kc], r + AQ_OFF);
            }
        }

        const uint32_t stg = sb + ASTG0 + (uint32_t)(st & 1) * ASTG_SZ;

#pragma unroll
        for (int sub = 0; sub < 2; sub++) {
            const int kt = st * 2 + sub;
            const uint32_t ksub = stg + AK + (uint32_t)(sub * 64 * ASTRIDE);
            const uint32_t vsub = stg + AV + (uint32_t)(sub * 64 * ASTRIDE);

            float sacc[8][4];
#pragma unroll
            for (int i = 0; i < 8; i++)
#pragma unroll
                for (int j = 0; j < 4; j++) sacc[i][j] = 0.0f;

#pragma unroll
            for (int kc = 0; kc < 4; kc++) {
                uint32_t kf[4][4];
#pragma unroll
                for (int ng = 0; ng < 4; ng++) {
                    uint32_t r = ksub + (uint32_t)(ng * 16 * ASTRIDE) + kc * 32 + b_off;
                    ldsm4(kf[ng], r);
                }
#pragma unroll
                for (int nt = 0; nt < 8; nt++)
                    mma16816(sacc[nt], qf[kc], &kf[nt >> 1][(nt & 1) * 2]);
            }

            if (kt * 64 + 63 > q0 + wid * 16) {
#pragma unroll
                for (int nt = 0; nt < 8; nt++) {
                    int colb = kt * 64 + nt * 8 + (lane & 3) * 2;
                    if (colb     > r0) sacc[nt][0] = -1e30f;
                    if (colb + 1 > r0) sacc[nt][1] = -1e30f;
                    if (colb     > r1) sacc[nt][2] = -1e30f;
                    if (colb + 1 > r1) sacc[nt][3] = -1e30f;
                }
            }

            float m0 = -1e30f, m1 = -1e30f;
#pragma unroll
            for (int nt = 0; nt < 8; nt++) {
                m0 = fmaxf(m0, fmaxf(sacc[nt][0], sacc[nt][1]));
                m1 = fmaxf(m1, fmaxf(sacc[nt][2], sacc[nt][3]));
            }
            m0 = fmaxf(m0, __shfl_xor_sync(0xffffffffu, m0, 1));
            m0 = fmaxf(m0, __shfl_xor_sync(0xffffffffu, m0, 2));
            m1 = fmaxf(m1, __shfl_xor_sync(0xffffffffu, m1, 1));
            m1 = fmaxf(m1, __shfl_xor_sync(0xffffffffu, m1, 2));

            float mn0 = fmaxf(mr0, m0), mn1 = fmaxf(mr1, m1);
            float al0 = ex2(mr0 - mn0), al1 = ex2(mr1 - mn1);
            mr0 = mn0; mr1 = mn1;

            uint32_t pA[8], pB[8];
            float s0 = 0.0f, s1 = 0.0f;
#pragma unroll
            for (int nt = 0; nt < 8; nt++) {
                float p0 = ex2(sacc[nt][0] - mn0);
                float p1 = ex2(sacc[nt][1] - mn0);
                float p2 = ex2(sacc[nt][2] - mn1);
                float p3 = ex2(sacc[nt][3] - mn1);
                s0 += p0 + p1;
                s1 += p2 + p3;
                pA[nt] = pack2(h16(p0), h16(p1));
                pB[nt] = pack2(h16(p2), h16(p3));
            }
            s0 += __shfl_xor_sync(0xffffffffu, s0, 1);
            s0 += __shfl_xor_sync(0xffffffffu, s0, 2);
            s1 += __shfl_xor_sync(0xffffffffu, s1, 1);
            s1 += __shfl_xor_sync(0xffffffffu, s1, 2);
            lr0 = lr0 * al0 + s0;
            lr1 = lr1 * al1 + s1;

#pragma unroll
            for (int dt = 0; dt < 8; dt++) {
                oacc[dt][0] *= al0; oacc[dt][1] *= al0;
                oacc[dt][2] *= al1; oacc[dt][3] *= al1;
            }

#pragma unroll
            for (int kc = 0; kc < 4; kc++) {
                uint32_t pf[4] = {pA[2 * kc], pB[2 * kc], pA[2 * kc + 1], pB[2 * kc + 1]};
                uint32_t vf[4][4];
#pragma unroll
                for (int dg = 0; dg < 4; dg++) {
                    uint32_t r = vsub + (uint32_t)(kc * 16 * ASTRIDE) + dg * 32 + v_off;
                    ldsm4t(vf[dg], r);
                }
#pragma unroll
                for (int dg = 0; dg < 4; dg++) {
                    mma16816(oacc[dg * 2],     pf, &vf[dg][0]);
                    mma16816(oacc[dg * 2 + 1], pf, &vf[dg][2]);
                }
            }
        }
    }

    const float inv0 = 1.0f / lr0, inv1 = 1.0f / lr1;
    const int b = bh >> 4, hh = bh & 15;
    size_t base0 = ((size_t)(b * LSEQ + r0)) * DMODEL + hh * KD + (lane & 3) * 2;
    size_t base1 = base0 + (size_t)8 * DMODEL;
#pragma unroll
    for (int dt = 0; dt < 8; dt++) {
        *(uint32_t*)(att16 + base0 + dt * 8) =
            pack2(h16(oacc[dt][0] * inv0), h16(oacc[dt][1] * inv0));
        *(uint32_t*)(att16 + base1 + dt * 8) =
            pack2(h16(oacc[dt][2] * inv1), h16(oacc[dt][3] * inv1));
    }
}

// ---------------------------------------------------------------------------
extern "C" void kernel_launch(void* const* d_in, const int* in_sizes, int n_in,
                              void* d_out, int out_size) {
    const float* x    = (const float*)d_in[0];
    const float* Wqkv = (const float*)d_in[1];
    const float* Wout = (const float*)d_in[2];
    float* out = (float*)d_out;

    __half *x16, *wq16, *wo16, *q16, *k16, *v16, *att16;
    cudaGetSymbolAddress((void**)&x16, g_x16);
    cudaGetSymbolAddress((void**)&wq16, g_wqkvT);
    cudaGetSymbolAddress((void**)&wo16, g_woutT);
    cudaGetSymbolAddress((void**)&q16, g_q16);
    cudaGetSymbolAddress((void**)&k16, g_k16);
    cudaGetSymbolAddress((void**)&v16, g_v16);
    cudaGetSymbolAddress((void**)&att16, g_att16);

    cudaFuncSetAttribute((const void*)gemm_mma_kernel<0>,
                         cudaFuncAttributeMaxDynamicSharedMemorySize, GEMM_SMEM);
    cudaFuncSetAttribute((const void*)gemm_mma_kernel<1>,
                         cudaFuncAttributeMaxDynamicSharedMemorySize, GEMM_SMEM);
    cudaFuncSetAttribute((const void*)attn_mma_kernel,
                         cudaFuncAttributeMaxDynamicSharedMemorySize, ATT_SMEM);

    // prep
    {
        int n4 = TOKENS * DMODEL / 4;
        convert_f16_kernel<<<(n4 + 255) / 256, 256>>>(x, x16, n4);
        transpose_f16_kernel<<<dim3(3 * DMODEL / 32, DMODEL / 32), dim3(32, 8)>>>(
            Wqkv, wq16, DMODEL, 3 * DMODEL);
        transpose_f16_kernel<<<dim3(DMODEL / 32, DMODEL / 32), dim3(32, 8)>>>(
            Wout, wo16, DMODEL, DMODEL);
    }

    // 1) qkv GEMM (persistent) -> fp16 head-major q/k/v
    gemm_mma_kernel<1><<<PERSIST_CTAS, 256, GEMM_SMEM>>>(
        x16, wq16, nullptr, q16, k16, v16, TOKENS, 3 * DMODEL, DMODEL);

    // 2) tensor-core causal flash attention -> att fp16
    attn_mma_kernel<<<dim3(LSEQ / 128, BH_CNT), 256, ATT_SMEM>>>(
        q16, k16, v16, att16);

    // 3) out = att @ Wout (persistent)
    gemm_mma_kernel<0><<<PERSIST_CTAS, 256, GEMM_SMEM>>>(
        att16, wo16, out, nullptr, nullptr, nullptr, TOKENS, DMODEL, DMODEL);
}

// round 13
// speedup vs baseline: 1.0323x; 1.0323x over previous
#include <cuda_runtime.h>
#include <cuda_fp16.h>
#include <cstdint>

// ----------------------------------------------------------------------------
// SelfAttention: out = Attn(x @ Wqkv) @ Wout, causal, H=16, Kd=64
// B=4, L=2048, D=1024 -> tokens = 8192
// R13: GEMM = 128x128 tile with 4 warps (64x64 warp tiles, 128B LDS/MMA)
//      at 2 CTA/SM (128 threads/CTA) — fat tiles + cross-CTA overlap.
//      Attention unchanged (R11). Pure fp16 HMMA, fp32 accum.
// ----------------------------------------------------------------------------

#define TOKENS 8192
#define LSEQ   2048
#define DMODEL 1024
#define HEADS  16
#define KD     64
#define BH_CNT (4 * HEADS)   // 64
#define PERSIST_CTAS 304     // 2 per SM

// ---------------- scratch ----------------------------------------------------
__device__ __half g_x16[(size_t)TOKENS * DMODEL];
__device__ __half g_wqkvT[(size_t)3 * DMODEL * DMODEL];
__device__ __half g_woutT[(size_t)DMODEL * DMODEL];
__device__ __half g_q16[(size_t)BH_CNT * LSEQ * KD];
__device__ __half g_k16[(size_t)BH_CNT * LSEQ * KD];
__device__ __half g_v16[(size_t)BH_CNT * LSEQ * KD];
__device__ __half g_att16[(size_t)TOKENS * DMODEL];

// ---------------- helpers ----------------------------------------------------
__device__ __forceinline__ uint32_t smem_u32(const void* p) {
    uint32_t a;
    asm("{ .reg .u64 t; cvta.to.shared.u64 t, %1; cvt.u32.u64 %0, t; }" : "=r"(a) : "l"(p));
    return a;
}
__device__ __forceinline__ void cp16(uint32_t s, const void* g) {
    asm volatile("cp.async.cg.shared.global [%0], [%1], 16;" :: "r"(s), "l"(g));
}
#define CP_COMMIT() asm volatile("cp.async.commit_group;" ::: "memory")
#define CP_WAIT0()  asm volatile("cp.async.wait_group 0;" ::: "memory")
#define CP_WAIT1()  asm volatile("cp.async.wait_group 1;" ::: "memory")

__device__ __forceinline__ void ldsm4(uint32_t* r, uint32_t addr) {
    asm volatile("ldmatrix.sync.aligned.m8n8.x4.shared.b16 {%0,%1,%2,%3}, [%4];"
                 : "=r"(r[0]), "=r"(r[1]), "=r"(r[2]), "=r"(r[3]) : "r"(addr));
}
__device__ __forceinline__ void ldsm4t(uint32_t* r, uint32_t addr) {
    asm volatile("ldmatrix.sync.aligned.m8n8.x4.trans.shared.b16 {%0,%1,%2,%3}, [%4];"
                 : "=r"(r[0]), "=r"(r[1]), "=r"(r[2]), "=r"(r[3]) : "r"(addr));
}
__device__ __forceinline__ void mma16816(float* c, const uint32_t* a, const uint32_t* b) {
    asm volatile("mma.sync.aligned.m16n8k16.row.col.f32.f16.f16.f32 "
                 "{%0,%1,%2,%3}, {%4,%5,%6,%7}, {%8,%9}, {%0,%1,%2,%3};"
                 : "+f"(c[0]), "+f"(c[1]), "+f"(c[2]), "+f"(c[3])
                 : "r"(a[0]), "r"(a[1]), "r"(a[2]), "r"(a[3]), "r"(b[0]), "r"(b[1]));
}
__device__ __forceinline__ float ex2(float x) {
    float y;
    asm("ex2.approx.f32 %0, %1;" : "=f"(y) : "f"(x));
    return y;
}
__device__ __forceinline__ unsigned short h16(float v) {
    return __half_as_ushort(__float2half_rn(v));
}
__device__ __forceinline__ uint32_t pack2(unsigned short a, unsigned short b) {
    return (uint32_t)a | ((uint32_t)b << 16);
}

// ---------------------------------------------------------------------------
// Prep kernels
// ---------------------------------------------------------------------------
__global__ void convert_f16_kernel(const float* __restrict__ in,
                                   __half* __restrict__ o16, int n4) {
    int i = blockIdx.x * blockDim.x + threadIdx.x;
    if (i >= n4) return;
    float4 v = ((const float4*)in)[i];
    ((ushort4*)o16)[i] = make_ushort4(h16(v.x), h16(v.y), h16(v.z), h16(v.w));
}

__global__ void transpose_f16_kernel(const float* __restrict__ W,
                                     __half* __restrict__ T16,
                                     int K, int N) {
    __shared__ float t[32][33];
    int n0 = blockIdx.x * 32, k0 = blockIdx.y * 32;
    int tx = threadIdx.x, ty = threadIdx.y;
#pragma unroll
    for (int j = 0; j < 4; j++) {
        int k = ty + j * 8;
        t[k][tx] = W[(size_t)(k0 + k) * N + n0 + tx];
    }
    __syncthreads();
#pragma unroll
    for (int j = 0; j < 4; j++) {
        int nl = ty + j * 8;
        T16[(size_t)(n0 + nl) * K + k0 + tx] = __ushort_as_half(h16(t[tx][nl]));
    }
}

// ---------------------------------------------------------------------------
// Persistent HMMA GEMM, pure fp16: C = A * B^T. 128x128 tile, 4 warps
// (2x2, 64x64 warp tile), BK=64, 3-stage cp.async pipeline, 2 CTA/SM.
// MODE 0: C fp32.  MODE 1: head-major fp16 q/k/v epilogue (q scaled).
// ---------------------------------------------------------------------------
#define GTHREADS 128
#define BM 128
#define BN 128
#define BK 64
#define RSTRIDE 144                    // 128B data + 16B pad
#define TILE_B  (128 * RSTRIDE)        // 18432
#define OFF_A   0
#define OFF_B   TILE_B
#define STAGE_B (2 * TILE_B)           // 36864
#define GEMM_SMEM (3 * STAGE_B)        // 110592
// Q scale: 1/sqrt(64) * log2(e)  (softmax runs in exp2 domain)
#define QSCALE (0.125f * 1.4426950408889634f)

template <int MODE>
__global__ __launch_bounds__(GTHREADS, 2) void gemm_mma_kernel(
    const __half* __restrict__ A, const __half* __restrict__ B,
    float* __restrict__ C,
    __half* __restrict__ q16, __half* __restrict__ k16, __half* __restrict__ v16,
    int M, int N, int K) {
    extern __shared__ __align__(128) char smem[];
    const uint32_t sb = smem_u32(smem);
    const int tid  = threadIdx.x;
    const int lane = tid & 31;
    const int wid  = tid >> 5;              // 0..3
    const int wm = (wid & 1) * 64;          // 2 m-groups
    const int wn = (wid >> 1) * 64;         // 2 n-groups
    const int NS = K / BK;                  // 16
    const int nmt = M / BM;
    const int ntiles = nmt * (N / BN);

    const uint32_t a_off = (uint32_t)((lane & 15) * RSTRIDE + (lane >> 4) * 16);
    const uint32_t b_off = (uint32_t)((((lane >> 4) & 1) * 8 + (lane & 7)) * RSTRIDE +
                                      ((lane >> 3) & 1) * 16);

    for (int t = blockIdx.x; t < ntiles; t += gridDim.x) {
        const int m0 = (t % nmt) * BM;
        const int n0 = (t / nmt) * BN;

        float acc[4][8][4];
#pragma unroll
        for (int i = 0; i < 4; i++)
#pragma unroll
            for (int j = 0; j < 8; j++)
#pragma unroll
                for (int q = 0; q < 4; q++) acc[i][j][q] = 0.0f;

        auto load_stage = [&](int s) {
            const uint32_t base = sb + (uint32_t)(s % 3) * STAGE_B;
            const int k0 = s * BK;
            // A + B: each 128 rows x 8 chunks of 16B = 1024 -> 8/thread each
            for (int i = tid; i < 1024; i += GTHREADS) {
                int row = i >> 3;
                int ch  = (i & 7) * 16;
                uint32_t so = (uint32_t)(row * RSTRIDE + ch);
                cp16(base + OFF_A + so, A + (size_t)(m0 + row) * K + k0 + (ch >> 1));
            }
            for (int i = tid; i < 1024; i += GTHREADS) {
                int row = i >> 3;
                int ch  = (i & 7) * 16;
                uint32_t so = (uint32_t)(row * RSTRIDE + ch);
                cp16(base + OFF_B + so, B + (size_t)(n0 + row) * K + k0 + (ch >> 1));
            }
            CP_COMMIT();
        };

        load_stage(0);
        load_stage(1);

        for (int s = 0; s < NS; s++) {
            if (s + 1 < NS) { CP_WAIT1(); }
            else            { CP_WAIT0(); }
            __syncthreads();
            if (s + 2 < NS) load_stage(s + 2);

            const uint32_t base = sb + (uint32_t)(s % 3) * STAGE_B;
#pragma unroll
            for (int kk = 0; kk < 4; kk++) {
                const uint32_t koff = kk * 32;
                uint32_t af[4][4], bf[4][4];
#pragma unroll
                for (int mt = 0; mt < 4; mt++) {
                    uint32_t r = base + (uint32_t)((wm + mt * 16) * RSTRIDE) + koff;
                    ldsm4(af[mt], r + OFF_A + a_off);
                }
#pragma unroll
                for (int ng = 0; ng < 4; ng++) {
                    uint32_t r = base + (uint32_t)((wn + ng * 16) * RSTRIDE) + koff;
                    ldsm4(bf[ng], r + OFF_B + b_off);
                }
#pragma unroll
                for (int mt = 0; mt < 4; mt++)
#pragma unroll
                    for (int nt = 0; nt < 8; nt++)
                        mma16816(acc[mt][nt], af[mt], &bf[nt >> 1][(nt & 1) * 2]);
            }
        }

        if (MODE == 0) {
#pragma unroll
            for (int mt = 0; mt < 4; mt++)
#pragma unroll
                for (int nt = 0; nt < 8; nt++) {
                    int row = m0 + wm + mt * 16 + (lane >> 2);
                    int col = n0 + wn + nt * 8 + (lane & 3) * 2;
                    *(float2*)&C[(size_t)row * N + col] =
                        make_float2(acc[mt][nt][0], acc[mt][nt][1]);
                    *(float2*)&C[(size_t)(row + 8) * N + col] =
                        make_float2(acc[mt][nt][2], acc[mt][nt][3]);
                }
        } else {
            const int sec = (n0 + wn) >> 10;          // 0=q 1=k 2=v
            const int hh  = ((n0 + wn) >> 6) & 15;
            __half* DST = (sec == 0) ? q16 : (sec == 1) ? k16 : v16;
            const float scl = (sec == 0) ? QSCALE : 1.0f;
#pragma unroll
            for (int mt = 0; mt < 4; mt++)
#pragma unroll
                for (int nt = 0; nt < 8; nt++) {
                    int row = m0 + wm + mt * 16 + (lane >> 2);
                    int d   = nt * 8 + (lane & 3) * 2;    // wn multiple of 64
                    int b   = row >> 11;
                    int ll  = row & 2047;
                    size_t idx = ((size_t)(b * HEADS + hh) * LSEQ + ll) * KD + d;
                    *(uint32_t*)(DST + idx) =
                        pack2(h16(acc[mt][nt][0] * scl), h16(acc[mt][nt][1] * scl));
                    *(uint32_t*)(DST + idx + (size_t)8 * KD) =
                        pack2(h16(acc[mt][nt][2] * scl), h16(acc[mt][nt][3] * scl));
                }
        }
        __syncthreads();   // all frag reads done before next tile's loads
    }
}

// ---------------------------------------------------------------------------
// Flash attention, pure fp16 MMA, causal, exp2 softmax (Q pre-scaled by
// log2(e)/8). 128-row kv stages, 2 CTA/SM, heavy q-tiles first. (R11)
// ---------------------------------------------------------------------------
#define ASTRIDE 144
#define AQ_OFF  0
#define ASTG0   (128 * ASTRIDE)        // 18432 (Q tile)
#define ASTG_SZ (2 * 128 * ASTRIDE)    // 36864 per stage (K, V: 128 rows each)
#define AK 0
#define AV (128 * ASTRIDE)
#define ATT_SMEM (ASTG0 + 2 * ASTG_SZ) // 92160

__global__ __launch_bounds__(256, 2) void attn_mma_kernel(
    const __half* __restrict__ q16,
    const __half* __restrict__ k16, const __half* __restrict__ v16,
    __half* __restrict__ att16) {
    extern __shared__ __align__(128) char smem[];
    const uint32_t sb = smem_u32(smem);
    const int tid  = threadIdx.x;
    const int lane = tid & 31;
    const int wid  = tid >> 5;
    const int qt   = gridDim.x - 1 - blockIdx.x;   // heavy tiles first
    const int bh   = blockIdx.y;
    const int q0   = qt * 128;
    const int nst  = qt + 1;

    const size_t hb = (size_t)bh * LSEQ * KD;
    const char* Qp = (const char*)(q16 + hb + (size_t)q0 * KD);
    const char* Kp = (const char*)(k16 + hb);
    const char* Vp = (const char*)(v16 + hb);

    auto load_q = [&]() {
        for (int i = tid; i < 1024; i += 256) {
            int row = i >> 3, ch = (i & 7) * 16;
            uint32_t so = (uint32_t)(row * ASTRIDE + ch);
            cp16(sb + AQ_OFF + so, Qp + (size_t)row * 128 + ch);
        }
    };
    auto load_stage = [&](int st) {
        const uint32_t base = sb + ASTG0 + (uint32_t)(st & 1) * ASTG_SZ;
        for (int i = tid; i < 1024; i += 256) {
            int row = i >> 3, ch = (i & 7) * 16;
            uint32_t so = (uint32_t)(row * ASTRIDE + ch);
            size_t go = (size_t)(st * 128 + row) * 128 + ch;
            cp16(base + AK + so, Kp + go);
            cp16(base + AV + so, Vp + go);
        }
        CP_COMMIT();
    };

    load_q();
    load_stage(0);

    const uint32_t a_off = (uint32_t)((lane & 15) * ASTRIDE + (lane >> 4) * 16);
    const uint32_t b_off = (uint32_t)((((lane >> 4) & 1) * 8 + (lane & 7)) * ASTRIDE +
                                      ((lane >> 3) & 1) * 16);
    const uint32_t v_off = (uint32_t)((lane & 15) * ASTRIDE + (lane >> 4) * 16);

    uint32_t qf[4][4];
    float oacc[8][4];
#pragma unroll
    for (int i = 0; i < 8; i++)
#pragma unroll
        for (int j = 0; j < 4; j++) oacc[i][j] = 0.0f;
    float mr0 = -1e30f, mr1 = -1e30f, lr0 = 0.0f, lr1 = 0.0f;

    const int r0 = q0 + wid * 16 + (lane >> 2);
    const int r1 = r0 + 8;

    for (int st = 0; st < nst; st++) {
        CP_WAIT0();
        __syncthreads();
        if (st + 1 < nst) load_stage(st + 1);

        if (st == 0) {
#pragma unroll
            for (int kc = 0; kc < 4; kc++) {
                uint32_t r = sb + (uint32_t)(wid * 16 * ASTRIDE) + kc * 32 + a_off;
                ldsm4(qf[kc], r + AQ_OFF);
            }
        }

        const uint32_t stg = sb + ASTG0 + (uint32_t)(st & 1) * ASTG_SZ;

#pragma unroll
        for (int sub = 0; sub < 2; sub++) {
            const int kt = st * 2 + sub;
            const uint32_t ksub = stg + AK + (uint32_t)(sub * 64 * ASTRIDE);
            const uint32_t vsub = stg + AV + (uint32_t)(sub * 64 * ASTRIDE);

            float sacc[8][4];
#pragma unroll
            for (int i = 0; i < 8; i++)
#pragma unroll
                for (int j = 0; j < 4; j++) sacc[i][j] = 0.0f;

#pragma unroll
            for (int kc = 0; kc < 4; kc++) {
                uint32_t kf[4][4];
#pragma unroll
                for (int ng = 0; ng < 4; ng++) {
                    uint32_t r = ksub + (uint32_t)(ng * 16 * ASTRIDE) + kc * 32 + b_off;
                    ldsm4(kf[ng], r);
                }
#pragma unroll
                for (int nt = 0; nt < 8; nt++)
                    mma16816(sacc[nt], qf[kc], &kf[nt >> 1][(nt & 1) * 2]);
            }

            if (kt * 64 + 63 > q0 + wid * 16) {
#pragma unroll
                for (int nt = 0; nt < 8; nt++) {
                    int colb = kt * 64 + nt * 8 + (lane & 3) * 2;
                    if (colb     > r0) sacc[nt][0] = -1e30f;
                    if (colb + 1 > r0) sacc[nt][1] = -1e30f;
                    if (colb     > r1) sacc[nt][2] = -1e30f;
                    if (colb + 1 > r1) sacc[nt][3] = -1e30f;
                }
            }

            float m0 = -1e30f, m1 = -1e30f;
#pragma unroll
            for (int nt = 0; nt < 8; nt++) {
                m0 = fmaxf(m0, fmaxf(sacc[nt][0], sacc[nt][1]));
                m1 = fmaxf(m1, fmaxf(sacc[nt][2], sacc[nt][3]));
            }
            m0 = fmaxf(m0, __shfl_xor_sync(0xffffffffu, m0, 1));
            m0 = fmaxf(m0, __shfl_xor_sync(0xffffffffu, m0, 2));
            m1 = fmaxf(m1, __shfl_xor_sync(0xffffffffu, m1, 1));
            m1 = fmaxf(m1, __shfl_xor_sync(0xffffffffu, m1, 2));

            float mn0 = fmaxf(mr0, m0), mn1 = fmaxf(mr1, m1);
            float al0 = ex2(mr0 - mn0), al1 = ex2(mr1 - mn1);
            mr0 = mn0; mr1 = mn1;

            uint32_t pA[8], pB[8];
            float s0 = 0.0f, s1 = 0.0f;
#pragma unroll
            for (int nt = 0; nt < 8; nt++) {
                float p0 = ex2(sacc[nt][0] - mn0);
                float p1 = ex2(sacc[nt][1] - mn0);
                float p2 = ex2(sacc[nt][2] - mn1);
                float p3 = ex2(sacc[nt][3] - mn1);
                s0 += p0 + p1;
                s1 += p2 + p3;
                pA[nt] = pack2(h16(p0), h16(p1));
                pB[nt] = pack2(h16(p2), h16(p3));
            }
            s0 += __shfl_xor_sync(0xffffffffu, s0, 1);
            s0 += __shfl_xor_sync(0xffffffffu, s0, 2);
            s1 += __shfl_xor_sync(0xffffffffu, s1, 1);
            s1 += __shfl_xor_sync(0xffffffffu, s1, 2);
            lr0 = lr0 * al0 + s0;
            lr1 = lr1 * al1 + s1;

#pragma unroll
            for (int dt = 0; dt < 8; dt++) {
                oacc[dt][0] *= al0; oacc[dt][1] *= al0;
                oacc[dt][2] *= al1; oacc[dt][3] *= al1;
            }

#pragma unroll
            for (int kc = 0; kc < 4; kc++) {
                uint32_t pf[4] = {pA[2 * kc], pB[2 * kc], pA[2 * kc + 1], pB[2 * kc + 1]};
                uint32_t vf[4][4];
#pragma unroll
                for (int dg = 0; dg < 4; dg++) {
                    uint32_t r = vsub + (uint32_t)(kc * 16 * ASTRIDE) + dg * 32 + v_off;
                    ldsm4t(vf[dg], r);
                }
#pragma unroll
                for (int dg = 0; dg < 4; dg++) {
                    mma16816(oacc[dg * 2],     pf, &vf[dg][0]);
                    mma16816(oacc[dg * 2 + 1], pf, &vf[dg][2]);
                }
            }
        }
    }

    const float inv0 = 1.0f / lr0, inv1 = 1.0f / lr1;
    const int b = bh >> 4, hh = bh & 15;
    size_t base0 = ((size_t)(b * LSEQ + r0)) * DMODEL + hh * KD + (lane & 3) * 2;
    size_t base1 = base0 + (size_t)8 * DMODEL;
#pragma unroll
    for (int dt = 0; dt < 8; dt++) {
        *(uint32_t*)(att16 + base0 + dt * 8) =
            pack2(h16(oacc[dt][0] * inv0), h16(oacc[dt][1] * inv0));
        *(uint32_t*)(att16 + base1 + dt * 8) =
            pack2(h16(oacc[dt][2] * inv1), h16(oacc[dt][3] * inv1));
    }
}

// ---------------------------------------------------------------------------
extern "C" void kernel_launch(void* const* d_in, const int* in_sizes, int n_in,
                              void* d_out, int out_size) {
    const float* x    = (const float*)d_in[0];
    const float* Wqkv = (const float*)d_in[1];
    const float* Wout = (const float*)d_in[2];
    float* out = (float*)d_out;

    __half *x16, *wq16, *wo16, *q16, *k16, *v16, *att16;
    cudaGetSymbolAddress((void**)&x16, g_x16);
    cudaGetSymbolAddress((void**)&wq16, g_wqkvT);
    cudaGetSymbolAddress((void**)&wo16, g_woutT);
    cudaGetSymbolAddress((void**)&q16, g_q16);
    cudaGetSymbolAddress((void**)&k16, g_k16);
    cudaGetSymbolAddress((void**)&v16, g_v16);
    cudaGetSymbolAddress((void**)&att16, g_att16);

    cudaFuncSetAttribute((const void*)gemm_mma_kernel<0>,
                         cudaFuncAttributeMaxDynamicSharedMemorySize, GEMM_SMEM);
    cudaFuncSetAttribute((const void*)gemm_mma_kernel<1>,
                         cudaFuncAttributeMaxDynamicSharedMemorySize, GEMM_SMEM);
    cudaFuncSetAttribute((const void*)attn_mma_kernel,
                         cudaFuncAttributeMaxDynamicSharedMemorySize, ATT_SMEM);

    // prep
    {
        int n4 = TOKENS * DMODEL / 4;
        convert_f16_kernel<<<(n4 + 255) / 256, 256>>>(x, x16, n4);
        transpose_f16_kernel<<<dim3(3 * DMODEL / 32, DMODEL / 32), dim3(32, 8)>>>(
            Wqkv, wq16, DMODEL, 3 * DMODEL);
        transpose_f16_kernel<<<dim3(DMODEL / 32, DMODEL / 32), dim3(32, 8)>>>(
            Wout, wo16, DMODEL, DMODEL);
    }

    // 1) qkv GEMM (persistent) -> fp16 head-major q/k/v
    gemm_mma_kernel<1><<<PERSIST_CTAS, GTHREADS, GEMM_SMEM>>>(
        x16, wq16, nullptr, q16, k16, v16, TOKENS, 3 * DMODEL, DMODEL);

    // 2) tensor-core causal flash attention -> att fp16
    attn_mma_kernel<<<dim3(LSEQ / 128, BH_CNT), 256, ATT_SMEM>>>(
        q16, k16, v16, att16);

    // 3) out = att @ Wout (persistent)
    gemm_mma_kernel<0><<<PERSIST_CTAS, GTHREADS, GEMM_SMEM>>>(
        att16, wo16, out, nullptr, nullptr, nullptr, TOKENS, DMODEL, DMODEL);
}

// round 14
// speedup vs baseline: 1.1106x; 1.0759x over previous
#include <cuda_runtime.h>
#include <cuda_fp16.h>
#include <cstdint>

// ----------------------------------------------------------------------------
// SelfAttention: out = Attn(x @ Wqkv) @ Wout, causal, H=16, Kd=64
// B=4, L=2048, D=1024 -> tokens = 8192
// R14: R11 GEMM (proven best) + MUFU-halved attention softmax:
//      ex2.approx.f16x2 producing packed P directly, row-sum l via MMA
//      against an all-ones fragment (numerator/denominator share p exactly).
// ----------------------------------------------------------------------------

#define TOKENS 8192
#define LSEQ   2048
#define DMODEL 1024
#define HEADS  16
#define KD     64
#define BH_CNT (4 * HEADS)   // 64
#define PERSIST_CTAS 304     // 2 per SM

// ---------------- scratch ----------------------------------------------------
__device__ __half g_x16[(size_t)TOKENS * DMODEL];
__device__ __half g_wqkvT[(size_t)3 * DMODEL * DMODEL];
__device__ __half g_woutT[(size_t)DMODEL * DMODEL];
__device__ __half g_q16[(size_t)BH_CNT * LSEQ * KD];
__device__ __half g_k16[(size_t)BH_CNT * LSEQ * KD];
__device__ __half g_v16[(size_t)BH_CNT * LSEQ * KD];
__device__ __half g_att16[(size_t)TOKENS * DMODEL];

// ---------------- helpers ----------------------------------------------------
__device__ __forceinline__ uint32_t smem_u32(const void* p) {
    uint32_t a;
    asm("{ .reg .u64 t; cvta.to.shared.u64 t, %1; cvt.u32.u64 %0, t; }" : "=r"(a) : "l"(p));
    return a;
}
__device__ __forceinline__ void cp16(uint32_t s, const void* g) {
    asm volatile("cp.async.cg.shared.global [%0], [%1], 16;" :: "r"(s), "l"(g));
}
#define CP_COMMIT() asm volatile("cp.async.commit_group;" ::: "memory")
#define CP_WAIT0()  asm volatile("cp.async.wait_group 0;" ::: "memory")
#define CP_WAIT1()  asm volatile("cp.async.wait_group 1;" ::: "memory")

__device__ __forceinline__ void ldsm4(uint32_t* r, uint32_t addr) {
    asm volatile("ldmatrix.sync.aligned.m8n8.x4.shared.b16 {%0,%1,%2,%3}, [%4];"
                 : "=r"(r[0]), "=r"(r[1]), "=r"(r[2]), "=r"(r[3]) : "r"(addr));
}
__device__ __forceinline__ void ldsm4t(uint32_t* r, uint32_t addr) {
    asm volatile("ldmatrix.sync.aligned.m8n8.x4.trans.shared.b16 {%0,%1,%2,%3}, [%4];"
                 : "=r"(r[0]), "=r"(r[1]), "=r"(r[2]), "=r"(r[3]) : "r"(addr));
}
__device__ __forceinline__ void mma16816(float* c, const uint32_t* a, const uint32_t* b) {
    asm volatile("mma.sync.aligned.m16n8k16.row.col.f32.f16.f16.f32 "
                 "{%0,%1,%2,%3}, {%4,%5,%6,%7}, {%8,%9}, {%0,%1,%2,%3};"
                 : "+f"(c[0]), "+f"(c[1]), "+f"(c[2]), "+f"(c[3])
                 : "r"(a[0]), "r"(a[1]), "r"(a[2]), "r"(a[3]), "r"(b[0]), "r"(b[1]));
}
__device__ __forceinline__ float ex2(float x) {
    float y;
    asm("ex2.approx.f32 %0, %1;" : "=f"(y) : "f"(x));
    return y;
}
// pack two fp32 into f16x2 (lo = a, hi = b), then exp2 both halves
__device__ __forceinline__ uint32_t ex2_pair(float a, float b) {
    uint32_t t, r;
    asm("cvt.rn.f16x2.f32 %0, %1, %2;" : "=r"(t) : "f"(b), "f"(a));
    asm("ex2.approx.f16x2 %0, %1;" : "=r"(r) : "r"(t));
    return r;
}
__device__ __forceinline__ unsigned short h16(float v) {
    return __half_as_ushort(__float2half_rn(v));
}
__device__ __forceinline__ uint32_t pack2(unsigned short a, unsigned short b) {
    return (uint32_t)a | ((uint32_t)b << 16);
}

// ---------------------------------------------------------------------------
// Prep kernels
// ---------------------------------------------------------------------------
__global__ void convert_f16_kernel(const float* __restrict__ in,
                                   __half* __restrict__ o16, int n4) {
    int i = blockIdx.x * blockDim.x + threadIdx.x;
    if (i >= n4) return;
    float4 v = ((const float4*)in)[i];
    ((ushort4*)o16)[i] = make_ushort4(h16(v.x), h16(v.y), h16(v.z), h16(v.w));
}

__global__ void transpose_f16_kernel(const float* __restrict__ W,
                                     __half* __restrict__ T16,
                                     int K, int N) {
    __shared__ float t[32][33];
    int n0 = blockIdx.x * 32, k0 = blockIdx.y * 32;
    int tx = threadIdx.x, ty = threadIdx.y;
#pragma unroll
    for (int j = 0; j < 4; j++) {
        int k = ty + j * 8;
        t[k][tx] = W[(size_t)(k0 + k) * N + n0 + tx];
    }
    __syncthreads();
#pragma unroll
    for (int j = 0; j < 4; j++) {
        int nl = ty + j * 8;
        T16[(size_t)(n0 + nl) * K + k0 + tx] = __ushort_as_half(h16(t[tx][nl]));
    }
}

// ---------------------------------------------------------------------------
// Persistent HMMA GEMM (R11 config): 128x128 tile, BK=64, 8 warps (64x32 warp
// tile), 3-stage cp.async pipeline, 2 CTA/SM, persistent grid of 304.
// MODE 0: C fp32.  MODE 1: head-major fp16 q/k/v epilogue (q scaled).
// ---------------------------------------------------------------------------
#define BM 128
#define BN 128
#define BK 64
#define RSTRIDE 144
#define TILE_B  (128 * RSTRIDE)        // 18432
#define OFF_A   0
#define OFF_B   TILE_B
#define STAGE_B (2 * TILE_B)           // 36864
#define GEMM_SMEM (3 * STAGE_B)        // 110592
// Q scale: 1/sqrt(64) * log2(e)  (softmax runs in exp2 domain)
#define QSCALE (0.125f * 1.4426950408889634f)

template <int MODE>
__global__ __launch_bounds__(256, 2) void gemm_mma_kernel(
    const __half* __restrict__ A, const __half* __restrict__ B,
    float* __restrict__ C,
    __half* __restrict__ q16, __half* __restrict__ k16, __half* __restrict__ v16,
    int M, int N, int K) {
    extern __shared__ __align__(128) char smem[];
    const uint32_t sb = smem_u32(smem);
    const int tid  = threadIdx.x;
    const int lane = tid & 31;
    const int wid  = tid >> 5;
    const int wm = (wid & 1) * 64;
    const int wn = (wid >> 1) * 32;
    const int NS = K / BK;             // 16
    const int nmt = M / BM;
    const int ntiles = nmt * (N / BN);

    const uint32_t a_off = (uint32_t)((lane & 15) * RSTRIDE + (lane >> 4) * 16);
    const uint32_t b_off = (uint32_t)((((lane >> 4) & 1) * 8 + (lane & 7)) * RSTRIDE +
                                      ((lane >> 3) & 1) * 16);

    for (int t = blockIdx.x; t < ntiles; t += gridDim.x) {
        const int m0 = (t % nmt) * BM;
        const int n0 = (t / nmt) * BN;

        float acc[4][4][4];
#pragma unroll
        for (int i = 0; i < 4; i++)
#pragma unroll
            for (int j = 0; j < 4; j++)
#pragma unroll
                for (int q = 0; q < 4; q++) acc[i][j][q] = 0.0f;

        auto load_stage = [&](int s) {
            const uint32_t base = sb + (uint32_t)(s % 3) * STAGE_B;
            const int k0 = s * BK;
            for (int i = tid; i < 1024; i += 256) {
                int row = i >> 3;
                int ch  = (i & 7) * 16;
                uint32_t so = (uint32_t)(row * RSTRIDE + ch);
                cp16(base + OFF_A + so, A + (size_t)(m0 + row) * K + k0 + (ch >> 1));
            }
            for (int i = tid; i < 1024; i += 256) {
                int row = i >> 3;
                int ch  = (i & 7) * 16;
                uint32_t so = (uint32_t)(row * RSTRIDE + ch);
                cp16(base + OFF_B + so, B + (size_t)(n0 + row) * K + k0 + (ch >> 1));
            }
            CP_COMMIT();
        };

        load_stage(0);
        load_stage(1);

        for (int s = 0; s < NS; s++) {
            if (s + 1 < NS) { CP_WAIT1(); }
            else            { CP_WAIT0(); }
            __syncthreads();
            if (s + 2 < NS) load_stage(s + 2);

            const uint32_t base = sb + (uint32_t)(s % 3) * STAGE_B;
#pragma unroll
            for (int kk = 0; kk < 4; kk++) {
                const uint32_t koff = kk * 32;
                uint32_t af[4][4], bf[2][4];
#pragma unroll
                for (int mt = 0; mt < 4; mt++) {
                    uint32_t r = base + (uint32_t)((wm + mt * 16) * RSTRIDE) + koff;
                    ldsm4(af[mt], r + OFF_A + a_off);
                }
#pragma unroll
                for (int ng = 0; ng < 2; ng++) {
                    uint32_t r = base + (uint32_t)((wn + ng * 16) * RSTRIDE) + koff;
                    ldsm4(bf[ng], r + OFF_B + b_off);
                }
#pragma unroll
                for (int mt = 0; mt < 4; mt++)
#pragma unroll
                    for (int nt = 0; nt < 4; nt++)
                        mma16816(acc[mt][nt], af[mt], &bf[nt >> 1][(nt & 1) * 2]);
            }
        }

        if (MODE == 0) {
#pragma unroll
            for (int mt = 0; mt < 4; mt++)
#pragma unroll
                for (int nt = 0; nt < 4; nt++) {
                    int row = m0 + wm + mt * 16 + (lane >> 2);
                    int col = n0 + wn + nt * 8 + (lane & 3) * 2;
                    *(float2*)&C[(size_t)row * N + col] =
                        make_float2(acc[mt][nt][0], acc[mt][nt][1]);
                    *(float2*)&C[(size_t)(row + 8) * N + col] =
                        make_float2(acc[mt][nt][2], acc[mt][nt][3]);
                }
        } else {
            const int sec = (n0 + wn) >> 10;          // 0=q 1=k 2=v
            const int hh  = ((n0 + wn) >> 6) & 15;
            __half* DST = (sec == 0) ? q16 : (sec == 1) ? k16 : v16;
            const float scl = (sec == 0) ? QSCALE : 1.0f;
#pragma unroll
            for (int mt = 0; mt < 4; mt++)
#pragma unroll
                for (int nt = 0; nt < 4; nt++) {
                    int row = m0 + wm + mt * 16 + (lane >> 2);
                    int d   = ((wn + nt * 8) & 63) + (lane & 3) * 2;
                    int b   = row >> 11;
                    int ll  = row & 2047;
                    size_t idx = ((size_t)(b * HEADS + hh) * LSEQ + ll) * KD + d;
                    *(uint32_t*)(DST + idx) =
                        pack2(h16(acc[mt][nt][0] * scl), h16(acc[mt][nt][1] * scl));
                    *(uint32_t*)(DST + idx + (size_t)8 * KD) =
                        pack2(h16(acc[mt][nt][2] * scl), h16(acc[mt][nt][3] * scl));
                }
        }
        __syncthreads();
    }
}

// ---------------------------------------------------------------------------
// Flash attention, pure fp16 MMA, causal. exp2 softmax in f16x2 (half the
// MUFU ops), row-sum l via MMA against ones. 128-row kv stages, 2 CTA/SM,
// heavy q-tiles first.
// ---------------------------------------------------------------------------
#define ASTRIDE 144
#define AQ_OFF  0
#define ASTG0   (128 * ASTRIDE)        // 18432 (Q tile)
#define ASTG_SZ (2 * 128 * ASTRIDE)    // 36864 per stage (K, V: 128 rows each)
#define AK 0
#define AV (128 * ASTRIDE)
#define ATT_SMEM (ASTG0 + 2 * ASTG_SZ) // 92160

__global__ __launch_bounds__(256, 2) void attn_mma_kernel(
    const __half* __restrict__ q16,
    const __half* __restrict__ k16, const __half* __restrict__ v16,
    __half* __restrict__ att16) {
    extern __shared__ __align__(128) char smem[];
    const uint32_t sb = smem_u32(smem);
    const int tid  = threadIdx.x;
    const int lane = tid & 31;
    const int wid  = tid >> 5;
    const int qt   = gridDim.x - 1 - blockIdx.x;   // heavy tiles first
    const int bh   = blockIdx.y;
    const int q0   = qt * 128;
    const int nst  = qt + 1;

    const size_t hb = (size_t)bh * LSEQ * KD;
    const char* Qp = (const char*)(q16 + hb + (size_t)q0 * KD);
    const char* Kp = (const char*)(k16 + hb);
    const char* Vp = (const char*)(v16 + hb);

    auto load_q = [&]() {
        for (int i = tid; i < 1024; i += 256) {
            int row = i >> 3, ch = (i & 7) * 16;
            uint32_t so = (uint32_t)(row * ASTRIDE + ch);
            cp16(sb + AQ_OFF + so, Qp + (size_t)row * 128 + ch);
        }
    };
    auto load_stage = [&](int st) {
        const uint32_t base = sb + ASTG0 + (uint32_t)(st & 1) * ASTG_SZ;
        for (int i = tid; i < 1024; i += 256) {
            int row = i >> 3, ch = (i & 7) * 16;
            uint32_t so = (uint32_t)(row * ASTRIDE + ch);
            size_t go = (size_t)(st * 128 + row) * 128 + ch;
            cp16(base + AK + so, Kp + go);
            cp16(base + AV + so, Vp + go);
        }
        CP_COMMIT();
    };

    load_q();
    load_stage(0);

    const uint32_t a_off = (uint32_t)((lane & 15) * ASTRIDE + (lane >> 4) * 16);
    const uint32_t b_off = (uint32_t)((((lane >> 4) & 1) * 8 + (lane & 7)) * ASTRIDE +
                                      ((lane >> 3) & 1) * 16);
    const uint32_t v_off = (uint32_t)((lane & 15) * ASTRIDE + (lane >> 4) * 16);

    uint32_t qf[4][4];
    float oacc[8][4];
    float lacc[4];   // row-sum accumulator via ones-MMA ([0]->r0, [2]->r1)
#pragma unroll
    for (int i = 0; i < 8; i++)
#pragma unroll
        for (int j = 0; j < 4; j++) oacc[i][j] = 0.0f;
#pragma unroll
    for (int j = 0; j < 4; j++) lacc[j] = 0.0f;
    float mr0 = -1e30f, mr1 = -1e30f;

    const uint32_t ones_b[2] = {0x3C003C00u, 0x3C003C00u};   // fp16 1.0 x4

    const int r0 = q0 + wid * 16 + (lane >> 2);
    const int r1 = r0 + 8;

    for (int st = 0; st < nst; st++) {
        CP_WAIT0();
        __syncthreads();
        if (st + 1 < nst) load_stage(st + 1);

        if (st == 0) {
#pragma unroll
            for (int kc = 0; kc < 4; kc++) {
                uint32_t r = sb + (uint32_t)(wid * 16 * ASTRIDE) + kc * 32 + a_off;
                ldsm4(qf[kc], r + AQ_OFF);
            }
        }

        const uint32_t stg = sb + ASTG0 + (uint32_t)(st & 1) * ASTG_SZ;

#pragma unroll
        for (int sub = 0; sub < 2; sub++) {
            const int kt = st * 2 + sub;
            const uint32_t ksub = stg + AK + (uint32_t)(sub * 64 * ASTRIDE);
            const uint32_t vsub = stg + AV + (uint32_t)(sub * 64 * ASTRIDE);

            // ---- S = Q K^T (Q pre-scaled by log2e/8) ----
            float sacc[8][4];
#pragma unroll
            for (int i = 0; i < 8; i++)
#pragma unroll
                for (int j = 0; j < 4; j++) sacc[i][j] = 0.0f;

#pragma unroll
            for (int kc = 0; kc < 4; kc++) {
                uint32_t kf[4][4];
#pragma unroll
                for (int ng = 0; ng < 4; ng++) {
                    uint32_t r = ksub + (uint32_t)(ng * 16 * ASTRIDE) + kc * 32 + b_off;
                    ldsm4(kf[ng], r);
                }
#pragma unroll
                for (int nt = 0; nt < 8; nt++)
                    mma16816(sacc[nt], qf[kc], &kf[nt >> 1][(nt & 1) * 2]);
            }

            // ---- causal mask (diagonal tiles only) ----
            if (kt * 64 + 63 > q0 + wid * 16) {
#pragma unroll
                for (int nt = 0; nt < 8; nt++) {
                    int colb = kt * 64 + nt * 8 + (lane & 3) * 2;
                    if (colb     > r0) sacc[nt][0] = -1e30f;
                    if (colb + 1 > r0) sacc[nt][1] = -1e30f;
                    if (colb     > r1) sacc[nt][2] = -1e30f;
                    if (colb + 1 > r1) sacc[nt][3] = -1e30f;
                }
            }

            // ---- online softmax: max, then f16x2 exp2 ----
            float m0 = -1e30f, m1 = -1e30f;
#pragma unroll
            for (int nt = 0; nt < 8; nt++) {
                m0 = fmaxf(m0, fmaxf(sacc[nt][0], sacc[nt][1]));
                m1 = fmaxf(m1, fmaxf(sacc[nt][2], sacc[nt][3]));
            }
            m0 = fmaxf(m0, __shfl_xor_sync(0xffffffffu, m0, 1));
            m0 = fmaxf(m0, __shfl_xor_sync(0xffffffffu, m0, 2));
            m1 = fmaxf(m1, __shfl_xor_sync(0xffffffffu, m1, 1));
            m1 = fmaxf(m1, __shfl_xor_sync(0xffffffffu, m1, 2));

            float mn0 = fmaxf(mr0, m0), mn1 = fmaxf(mr1, m1);
            float al0 = ex2(mr0 - mn0), al1 = ex2(mr1 - mn1);
            mr0 = mn0; mr1 = mn1;

            uint32_t pA[8], pB[8];
#pragma unroll
            for (int nt = 0; nt < 8; nt++) {
                pA[nt] = ex2_pair(sacc[nt][0] - mn0, sacc[nt][1] - mn0);
                pB[nt] = ex2_pair(sacc[nt][2] - mn1, sacc[nt][3] - mn1);
            }

            // rescale running O and l
#pragma unroll
            for (int dt = 0; dt < 8; dt++) {
                oacc[dt][0] *= al0; oacc[dt][1] *= al0;
                oacc[dt][2] *= al1; oacc[dt][3] *= al1;
            }
            lacc[0] *= al0; lacc[1] *= al0;
            lacc[2] *= al1; lacc[3] *= al1;

            // ---- O += P V  and  l += P * ones ----
#pragma unroll
            for (int kc = 0; kc < 4; kc++) {
                uint32_t pf[4] = {pA[2 * kc], pB[2 * kc], pA[2 * kc + 1], pB[2 * kc + 1]};
                uint32_t vf[4][4];
#pragma unroll
                for (int dg = 0; dg < 4; dg++) {
                    uint32_t r = vsub + (uint32_t)(kc * 16 * ASTRIDE) + dg * 32 + v_off;
                    ldsm4t(vf[dg], r);
                }
                mma16816(lacc, pf, ones_b);
#pragma unroll
                for (int dg = 0; dg < 4; dg++) {
                    mma16816(oacc[dg * 2],     pf, &vf[dg][0]);
                    mma16816(oacc[dg * 2 + 1], pf, &vf[dg][2]);
                }
            }
        }
    }

    // ---- epilogue ----
    const float inv0 = 1.0f / lacc[0], inv1 = 1.0f / lacc[2];
    const int b = bh >> 4, hh = bh & 15;
    size_t base0 = ((size_t)(b * LSEQ + r0)) * DMODEL + hh * KD + (lane & 3) * 2;
    size_t base1 = base0 + (size_t)8 * DMODEL;
#pragma unroll
    for (int dt = 0; dt < 8; dt++) {
        *(uint32_t*)(att16 + base0 + dt * 8) =
            pack2(h16(oacc[dt][0] * inv0), h16(oacc[dt][1] * inv0));
        *(uint32_t*)(att16 + base1 + dt * 8) =
            pack2(h16(oacc[dt][2] * inv1), h16(oacc[dt][3] * inv1));
    }
}

// ---------------------------------------------------------------------------
extern "C" void kernel_launch(void* const* d_in, const int* in_sizes, int n_in,
                              void* d_out, int out_size) {
    const float* x    = (const float*)d_in[0];
    const float* Wqkv = (const float*)d_in[1];
    const float* Wout = (const float*)d_in[2];
    float* out = (float*)d_out;

    __half *x16, *wq16, *wo16, *q16, *k16, *v16, *att16;
    cudaGetSymbolAddress((void**)&x16, g_x16);
    cudaGetSymbolAddress((void**)&wq16, g_wqkvT);
    cudaGetSymbolAddress((void**)&wo16, g_woutT);
    cudaGetSymbolAddress((void**)&q16, g_q16);
    cudaGetSymbolAddress((void**)&k16, g_k16);
    cudaGetSymbolAddress((void**)&v16, g_v16);
    cudaGetSymbolAddress((void**)&att16, g_att16);

    cudaFuncSetAttribute((const void*)gemm_mma_kernel<0>,
                         cudaFuncAttributeMaxDynamicSharedMemorySize, GEMM_SMEM);
    cudaFuncSetAttribute((const void*)gemm_mma_kernel<1>,
                         cudaFuncAttributeMaxDynamicSharedMemorySize, GEMM_SMEM);
    cudaFuncSetAttribute((const void*)attn_mma_kernel,
                         cudaFuncAttributeMaxDynamicSharedMemorySize, ATT_SMEM);

    // prep
    {
        int n4 = TOKENS * DMODEL / 4;
        convert_f16_kernel<<<(n4 + 255) / 256, 256>>>(x, x16, n4);
        transpose_f16_kernel<<<dim3(3 * DMODEL / 32, DMODEL / 32), dim3(32, 8)>>>(
            Wqkv, wq16, DMODEL, 3 * DMODEL);
        transpose_f16_kernel<<<dim3(DMODEL / 32, DMODEL / 32), dim3(32, 8)>>>(
            Wout, wo16, DMODEL, DMODEL);
    }

    // 1) qkv GEMM (persistent) -> fp16 head-major q/k/v
    gemm_mma_kernel<1><<<PERSIST_CTAS, 256, GEMM_SMEM>>>(
        x16, wq16, nullptr, q16, k16, v16, TOKENS, 3 * DMODEL, DMODEL);

    // 2) tensor-core causal flash attention -> att fp16
    attn_mma_kernel<<<dim3(LSEQ / 128, BH_CNT), 256, ATT_SMEM>>>(
        q16, k16, v16, att16);

    // 3) out = att @ Wout (persistent)
    gemm_mma_kernel<0><<<PERSIST_CTAS, 256, GEMM_SMEM>>>(
        att16, wo16, out, nullptr, nullptr, nullptr, TOKENS, DMODEL, DMODEL);
}

// round 15
// speedup vs baseline: 1.1293x; 1.0168x over previous
#include <cuda_runtime.h>
#include <cuda_fp16.h>
#include <cstdint>

// ----------------------------------------------------------------------------
// SelfAttention: out = Attn(x @ Wqkv) @ Wout, causal, H=16, Kd=64
// B=4, L=2048, D=1024 -> tokens = 8192
// R15: R14 + attention 4-deep 64-row cp.async ring (3-stage prefetch distance)
//      + merged single prep kernel. GEMM unchanged (R11 config, proven best).
// ----------------------------------------------------------------------------

#define TOKENS 8192
#define LSEQ   2048
#define DMODEL 1024
#define HEADS  16
#define KD     64
#define BH_CNT (4 * HEADS)   // 64
#define PERSIST_CTAS 304     // 2 per SM

// ---------------- scratch ----------------------------------------------------
__device__ __half g_x16[(size_t)TOKENS * DMODEL];
__device__ __half g_wqkvT[(size_t)3 * DMODEL * DMODEL];
__device__ __half g_woutT[(size_t)DMODEL * DMODEL];
__device__ __half g_q16[(size_t)BH_CNT * LSEQ * KD];
__device__ __half g_k16[(size_t)BH_CNT * LSEQ * KD];
__device__ __half g_v16[(size_t)BH_CNT * LSEQ * KD];
__device__ __half g_att16[(size_t)TOKENS * DMODEL];

// ---------------- helpers ----------------------------------------------------
__device__ __forceinline__ uint32_t smem_u32(const void* p) {
    uint32_t a;
    asm("{ .reg .u64 t; cvta.to.shared.u64 t, %1; cvt.u32.u64 %0, t; }" : "=r"(a) : "l"(p));
    return a;
}
__device__ __forceinline__ void cp16(uint32_t s, const void* g) {
    asm volatile("cp.async.cg.shared.global [%0], [%1], 16;" :: "r"(s), "l"(g));
}
#define CP_COMMIT() asm volatile("cp.async.commit_group;" ::: "memory")
#define CP_WAIT0()  asm volatile("cp.async.wait_group 0;" ::: "memory")
#define CP_WAIT1()  asm volatile("cp.async.wait_group 1;" ::: "memory")
#define CP_WAIT2()  asm volatile("cp.async.wait_group 2;" ::: "memory")

__device__ __forceinline__ void ldsm4(uint32_t* r, uint32_t addr) {
    asm volatile("ldmatrix.sync.aligned.m8n8.x4.shared.b16 {%0,%1,%2,%3}, [%4];"
                 : "=r"(r[0]), "=r"(r[1]), "=r"(r[2]), "=r"(r[3]) : "r"(addr));
}
__device__ __forceinline__ void ldsm4t(uint32_t* r, uint32_t addr) {
    asm volatile("ldmatrix.sync.aligned.m8n8.x4.trans.shared.b16 {%0,%1,%2,%3}, [%4];"
                 : "=r"(r[0]), "=r"(r[1]), "=r"(r[2]), "=r"(r[3]) : "r"(addr));
}
__device__ __forceinline__ void mma16816(float* c, const uint32_t* a, const uint32_t* b) {
    asm volatile("mma.sync.aligned.m16n8k16.row.col.f32.f16.f16.f32 "
                 "{%0,%1,%2,%3}, {%4,%5,%6,%7}, {%8,%9}, {%0,%1,%2,%3};"
                 : "+f"(c[0]), "+f"(c[1]), "+f"(c[2]), "+f"(c[3])
                 : "r"(a[0]), "r"(a[1]), "r"(a[2]), "r"(a[3]), "r"(b[0]), "r"(b[1]));
}
__device__ __forceinline__ float ex2(float x) {
    float y;
    asm("ex2.approx.f32 %0, %1;" : "=f"(y) : "f"(x));
    return y;
}
__device__ __forceinline__ uint32_t ex2_pair(float a, float b) {
    uint32_t t, r;
    asm("cvt.rn.f16x2.f32 %0, %1, %2;" : "=r"(t) : "f"(b), "f"(a));
    asm("ex2.approx.f16x2 %0, %1;" : "=r"(r) : "r"(t));
    return r;
}
__device__ __forceinline__ unsigned short h16(float v) {
    return __half_as_ushort(__float2half_rn(v));
}
__device__ __forceinline__ uint32_t pack2(unsigned short a, unsigned short b) {
    return (uint32_t)a | ((uint32_t)b << 16);
}

// ---------------------------------------------------------------------------
// Merged prep kernel: one launch.
//   blocks [0, NCONV)              : x fp32 -> fp16
//   blocks [NCONV, NCONV+NTQ)      : Wqkv transpose -> fp16 [N,K]
//   blocks [NCONV+NTQ, +NTO)       : Wout transpose -> fp16 [N,K]
// ---------------------------------------------------------------------------
#define NCONV (TOKENS * DMODEL / 4 / 256)                    // 8192
#define NTQ   ((3 * DMODEL / 32) * (DMODEL / 32))            // 3072
#define NTO   ((DMODEL / 32) * (DMODEL / 32))                // 1024

__global__ void prep_kernel(const float* __restrict__ x,
                            const float* __restrict__ Wqkv,
                            const float* __restrict__ Wout,
                            __half* __restrict__ x16,
                            __half* __restrict__ wq16,
                            __half* __restrict__ wo16) {
    int blk = blockIdx.x;
    if (blk < NCONV) {
        int i = blk * 256 + threadIdx.x;
        float4 v = ((const float4*)x)[i];
        ((ushort4*)x16)[i] = make_ushort4(h16(v.x), h16(v.y), h16(v.z), h16(v.w));
        return;
    }
    // transpose jobs: 32x32 tile, 256 threads as (32, 8)
    __shared__ float t[32][33];
    const float* W;
    __half* T16;
    int K = DMODEL, N, tile;
    if (blk < NCONV + NTQ) {
        W = Wqkv; T16 = wq16; N = 3 * DMODEL; tile = blk - NCONV;
    } else {
        W = Wout; T16 = wo16; N = DMODEL; tile = blk - NCONV - NTQ;
    }
    int ntx = N / 32;
    int n0 = (tile % ntx) * 32, k0 = (tile / ntx) * 32;
    int tx = threadIdx.x & 31, ty = threadIdx.x >> 5;
#pragma unroll
    for (int j = 0; j < 4; j++) {
        int k = ty + j * 8;
        t[k][tx] = W[(size_t)(k0 + k) * N + n0 + tx];
    }
    __syncthreads();
#pragma unroll
    for (int j = 0; j < 4; j++) {
        int nl = ty + j * 8;
        T16[(size_t)(n0 + nl) * K + k0 + tx] = __ushort_as_half(h16(t[tx][nl]));
    }
}

// ---------------------------------------------------------------------------
// Persistent HMMA GEMM (R11 config): 128x128 tile, BK=64, 8 warps (64x32 warp
// tile), 3-stage cp.async pipeline, 2 CTA/SM, persistent grid of 304.
// MODE 0: C fp32.  MODE 1: head-major fp16 q/k/v epilogue (q scaled).
// ---------------------------------------------------------------------------
#define BM 128
#define BN 128
#define BK 64
#define RSTRIDE 144
#define TILE_B  (128 * RSTRIDE)        // 18432
#define OFF_A   0
#define OFF_B   TILE_B
#define STAGE_B (2 * TILE_B)           // 36864
#define GEMM_SMEM (3 * STAGE_B)        // 110592
#define QSCALE (0.125f * 1.4426950408889634f)

template <int MODE>
__global__ __launch_bounds__(256, 2) void gemm_mma_kernel(
    const __half* __restrict__ A, const __half* __restrict__ B,
    float* __restrict__ C,
    __half* __restrict__ q16, __half* __restrict__ k16, __half* __restrict__ v16,
    int M, int N, int K) {
    extern __shared__ __align__(128) char smem[];
    const uint32_t sb = smem_u32(smem);
    const int tid  = threadIdx.x;
    const int lane = tid & 31;
    const int wid  = tid >> 5;
    const int wm = (wid & 1) * 64;
    const int wn = (wid >> 1) * 32;
    const int NS = K / BK;             // 16
    const int nmt = M / BM;
    const int ntiles = nmt * (N / BN);

    const uint32_t a_off = (uint32_t)((lane & 15) * RSTRIDE + (lane >> 4) * 16);
    const uint32_t b_off = (uint32_t)((((lane >> 4) & 1) * 8 + (lane & 7)) * RSTRIDE +
                                      ((lane >> 3) & 1) * 16);

    for (int t = blockIdx.x; t < ntiles; t += gridDim.x) {
        const int m0 = (t % nmt) * BM;
        const int n0 = (t / nmt) * BN;

        float acc[4][4][4];
#pragma unroll
        for (int i = 0; i < 4; i++)
#pragma unroll
            for (int j = 0; j < 4; j++)
#pragma unroll
                for (int q = 0; q < 4; q++) acc[i][j][q] = 0.0f;

        auto load_stage = [&](int s) {
            const uint32_t base = sb + (uint32_t)(s % 3) * STAGE_B;
            const int k0 = s * BK;
            for (int i = tid; i < 1024; i += 256) {
                int row = i >> 3;
                int ch  = (i & 7) * 16;
                uint32_t so = (uint32_t)(row * RSTRIDE + ch);
                cp16(base + OFF_A + so, A + (size_t)(m0 + row) * K + k0 + (ch >> 1));
            }
            for (int i = tid; i < 1024; i += 256) {
                int row = i >> 3;
                int ch  = (i & 7) * 16;
                uint32_t so = (uint32_t)(row * RSTRIDE + ch);
                cp16(base + OFF_B + so, B + (size_t)(n0 + row) * K + k0 + (ch >> 1));
            }
            CP_COMMIT();
        };

        load_stage(0);
        load_stage(1);

        for (int s = 0; s < NS; s++) {
            if (s + 1 < NS) { CP_WAIT1(); }
            else            { CP_WAIT0(); }
            __syncthreads();
            if (s + 2 < NS) load_stage(s + 2);

            const uint32_t base = sb + (uint32_t)(s % 3) * STAGE_B;
#pragma unroll
            for (int kk = 0; kk < 4; kk++) {
                const uint32_t koff = kk * 32;
                uint32_t af[4][4], bf[2][4];
#pragma unroll
                for (int mt = 0; mt < 4; mt++) {
                    uint32_t r = base + (uint32_t)((wm + mt * 16) * RSTRIDE) + koff;
                    ldsm4(af[mt], r + OFF_A + a_off);
                }
#pragma unroll
                for (int ng = 0; ng < 2; ng++) {
                    uint32_t r = base + (uint32_t)((wn + ng * 16) * RSTRIDE) + koff;
                    ldsm4(bf[ng], r + OFF_B + b_off);
                }
#pragma unroll
                for (int mt = 0; mt < 4; mt++)
#pragma unroll
                    for (int nt = 0; nt < 4; nt++)
                        mma16816(acc[mt][nt], af[mt], &bf[nt >> 1][(nt & 1) * 2]);
            }
        }

        if (MODE == 0) {
#pragma unroll
            for (int mt = 0; mt < 4; mt++)
#pragma unroll
                for (int nt = 0; nt < 4; nt++) {
                    int row = m0 + wm + mt * 16 + (lane >> 2);
                    int col = n0 + wn + nt * 8 + (lane & 3) * 2;
                    *(float2*)&C[(size_t)row * N + col] =
                        make_float2(acc[mt][nt][0], acc[mt][nt][1]);
                    *(float2*)&C[(size_t)(row + 8) * N + col] =
                        make_float2(acc[mt][nt][2], acc[mt][nt][3]);
                }
        } else {
            const int sec = (n0 + wn) >> 10;          // 0=q 1=k 2=v
            const int hh  = ((n0 + wn) >> 6) & 15;
            __half* DST = (sec == 0) ? q16 : (sec == 1) ? k16 : v16;
            const float scl = (sec == 0) ? QSCALE : 1.0f;
#pragma unroll
            for (int mt = 0; mt < 4; mt++)
#pragma unroll
                for (int nt = 0; nt < 4; nt++) {
                    int row = m0 + wm + mt * 16 + (lane >> 2);
                    int d   = ((wn + nt * 8) & 63) + (lane & 3) * 2;
                    int b   = row >> 11;
                    int ll  = row & 2047;
                    size_t idx = ((size_t)(b * HEADS + hh) * LSEQ + ll) * KD + d;
                    *(uint32_t*)(DST + idx) =
                        pack2(h16(acc[mt][nt][0] * scl), h16(acc[mt][nt][1] * scl));
                    *(uint32_t*)(DST + idx + (size_t)8 * KD) =
                        pack2(h16(acc[mt][nt][2] * scl), h16(acc[mt][nt][3] * scl));
                }
        }
        __syncthreads();
    }
}

// ---------------------------------------------------------------------------
// Flash attention, pure fp16 MMA, causal. f16x2 exp2 softmax, l via ones-MMA.
// 4-deep ring of 64-row kv stages (3 stages prefetch ahead), 2 CTA/SM,
// heavy q-tiles first. One commit per iteration (empty near tail).
// ---------------------------------------------------------------------------
#define ASTRIDE 144
#define AQ_OFF  0
#define ASTG0   (128 * ASTRIDE)        // 18432 (Q tile)
#define ASTG_SZ (2 * 64 * ASTRIDE)     // 18432 per stage (K 64 rows, V 64 rows)
#define AK 0
#define AV (64 * ASTRIDE)
#define ATT_SMEM (ASTG0 + 4 * ASTG_SZ) // 92160

__global__ __launch_bounds__(256, 2) void attn_mma_kernel(
    const __half* __restrict__ q16,
    const __half* __restrict__ k16, const __half* __restrict__ v16,
    __half* __restrict__ att16) {
    extern __shared__ __align__(128) char smem[];
    const uint32_t sb = smem_u32(smem);
    const int tid  = threadIdx.x;
    const int lane = tid & 31;
    const int wid  = tid >> 5;
    const int qt   = gridDim.x - 1 - blockIdx.x;   // heavy tiles first
    const int bh   = blockIdx.y;
    const int q0   = qt * 128;
    const int nkv  = 2 * qt + 2;                   // 64-row subtiles

    const size_t hb = (size_t)bh * LSEQ * KD;
    const char* Qp = (const char*)(q16 + hb + (size_t)q0 * KD);
    const char* Kp = (const char*)(k16 + hb);
    const char* Vp = (const char*)(v16 + hb);

    auto load_q = [&]() {
        for (int i = tid; i < 1024; i += 256) {
            int row = i >> 3, ch = (i & 7) * 16;
            uint32_t so = (uint32_t)(row * ASTRIDE + ch);
            cp16(sb + AQ_OFF + so, Qp + (size_t)row * 128 + ch);
        }
    };
    // load one 64-row kv stage into ring slot kt%4; always commits one group
    auto load_stage = [&](int kt) {
        if (kt < nkv) {
            const uint32_t base = sb + ASTG0 + (uint32_t)(kt & 3) * ASTG_SZ;
            for (int i = tid; i < 512; i += 256) {
                int row = i >> 3, ch = (i & 7) * 16;
                uint32_t so = (uint32_t)(row * ASTRIDE + ch);
                size_t go = (size_t)(kt * 64 + row) * 128 + ch;
                cp16(base + AK + so, Kp + go);
                cp16(base + AV + so, Vp + go);
            }
        }
        CP_COMMIT();
    };

    load_q();
    load_stage(0);   // group 0: Q + stage0
    load_stage(1);   // group 1
    load_stage(2);   // group 2

    const uint32_t a_off = (uint32_t)((lane & 15) * ASTRIDE + (lane >> 4) * 16);
    const uint32_t b_off = (uint32_t)((((lane >> 4) & 1) * 8 + (lane & 7)) * ASTRIDE +
                                      ((lane >> 3) & 1) * 16);
    const uint32_t v_off = (uint32_t)((lane & 15) * ASTRIDE + (lane >> 4) * 16);

    uint32_t qf[4][4];
    float oacc[8][4];
    float lacc[4];
#pragma unroll
    for (int i = 0; i < 8; i++)
#pragma unroll
        for (int j = 0; j < 4; j++) oacc[i][j] = 0.0f;
#pragma unroll
    for (int j = 0; j < 4; j++) lacc[j] = 0.0f;
    float mr0 = -1e30f, mr1 = -1e30f;

    const uint32_t ones_b[2] = {0x3C003C00u, 0x3C003C00u};

    const int r0 = q0 + wid * 16 + (lane >> 2);
    const int r1 = r0 + 8;

    for (int kt = 0; kt < nkv; kt++) {
        CP_WAIT2();          // stage kt complete (2 newer groups may be in flight)
        __syncthreads();     // ring slot (kt+3)%4's readers (iter kt-1) are done
        load_stage(kt + 3);  // keeps exactly one commit per iteration

        if (kt == 0) {
#pragma unroll
            for (int kc = 0; kc < 4; kc++) {
                uint32_t r = sb + (uint32_t)(wid * 16 * ASTRIDE) + kc * 32 + a_off;
                ldsm4(qf[kc], r + AQ_OFF);
            }
        }

        const uint32_t stg  = sb + ASTG0 + (uint32_t)(kt & 3) * ASTG_SZ;
        const uint32_t ksub = stg + AK;
        const uint32_t vsub = stg + AV;

        // ---- S = Q K^T (Q pre-scaled by log2e/8) ----
        float sacc[8][4];
#pragma unroll
        for (int i = 0; i < 8; i++)
#pragma unroll
            for (int j = 0; j < 4; j++) sacc[i][j] = 0.0f;

#pragma unroll
        for (int kc = 0; kc < 4; kc++) {
            uint32_t kf[4][4];
#pragma unroll
            for (int ng = 0; ng < 4; ng++) {
                uint32_t r = ksub + (uint32_t)(ng * 16 * ASTRIDE) + kc * 32 + b_off;
                ldsm4(kf[ng], r);
            }
#pragma unroll
            for (int nt = 0; nt < 8; nt++)
                mma16816(sacc[nt], qf[kc], &kf[nt >> 1][(nt & 1) * 2]);
        }

        // ---- causal mask (diagonal tiles only) ----
        if (kt * 64 + 63 > q0 + wid * 16) {
#pragma unroll
            for (int nt = 0; nt < 8; nt++) {
                int colb = kt * 64 + nt * 8 + (lane & 3) * 2;
                if (colb     > r0) sacc[nt][0] = -1e30f;
                if (colb + 1 > r0) sacc[nt][1] = -1e30f;
                if (colb     > r1) sacc[nt][2] = -1e30f;
                if (colb + 1 > r1) sacc[nt][3] = -1e30f;
            }
        }

        // ---- online softmax: max, then f16x2 exp2 ----
        float m0 = -1e30f, m1 = -1e30f;
#pragma unroll
        for (int nt = 0; nt < 8; nt++) {
            m0 = fmaxf(m0, fmaxf(sacc[nt][0], sacc[nt][1]));
            m1 = fmaxf(m1, fmaxf(sacc[nt][2], sacc[nt][3]));
        }
        m0 = fmaxf(m0, __shfl_xor_sync(0xffffffffu, m0, 1));
        m0 = fmaxf(m0, __shfl_xor_sync(0xffffffffu, m0, 2));
        m1 = fmaxf(m1, __shfl_xor_sync(0xffffffffu, m1, 1));
        m1 = fmaxf(m1, __shfl_xor_sync(0xffffffffu, m1, 2));

        float mn0 = fmaxf(mr0, m0), mn1 = fmaxf(mr1, m1);
        float al0 = ex2(mr0 - mn0), al1 = ex2(mr1 - mn1);
        mr0 = mn0; mr1 = mn1;

        uint32_t pA[8], pB[8];
#pragma unroll
        for (int nt = 0; nt < 8; nt++) {
            pA[nt] = ex2_pair(sacc[nt][0] - mn0, sacc[nt][1] - mn0);
            pB[nt] = ex2_pair(sacc[nt][2] - mn1, sacc[nt][3] - mn1);
        }

#pragma unroll
        for (int dt = 0; dt < 8; dt++) {
            oacc[dt][0] *= al0; oacc[dt][1] *= al0;
            oacc[dt][2] *= al1; oacc[dt][3] *= al1;
        }
        lacc[0] *= al0; lacc[1] *= al0;
        lacc[2] *= al1; lacc[3] *= al1;

        // ---- O += P V  and  l += P * ones ----
#pragma unroll
        for (int kc = 0; kc < 4; kc++) {
            uint32_t pf[4] = {pA[2 * kc], pB[2 * kc], pA[2 * kc + 1], pB[2 * kc + 1]};
            uint32_t vf[4][4];
#pragma unroll
            for (int dg = 0; dg < 4; dg++) {
                uint32_t r = vsub + (uint32_t)(kc * 16 * ASTRIDE) + dg * 32 + v_off;
                ldsm4t(vf[dg], r);
            }
            mma16816(lacc, pf, ones_b);
#pragma unroll
            for (int dg = 0; dg < 4; dg++) {
                mma16816(oacc[dg * 2],     pf, &vf[dg][0]);
                mma16816(oacc[dg * 2 + 1], pf, &vf[dg][2]);
            }
        }
    }

    // ---- epilogue ----
    const float inv0 = 1.0f / lacc[0], inv1 = 1.0f / lacc[2];
    const int b = bh >> 4, hh = bh & 15;
    size_t base0 = ((size_t)(b * LSEQ + r0)) * DMODEL + hh * KD + (lane & 3) * 2;
    size_t base1 = base0 + (size_t)8 * DMODEL;
#pragma unroll
    for (int dt = 0; dt < 8; dt++) {
        *(uint32_t*)(att16 + base0 + dt * 8) =
            pack2(h16(oacc[dt][0] * inv0), h16(oacc[dt][1] * inv0));
        *(uint32_t*)(att16 + base1 + dt * 8) =
            pack2(h16(oacc[dt][2] * inv1), h16(oacc[dt][3] * inv1));
    }
}

// ---------------------------------------------------------------------------
extern "C" void kernel_launch(void* const* d_in, const int* in_sizes, int n_in,
                              void* d_out, int out_size) {
    const float* x    = (const float*)d_in[0];
    const float* Wqkv = (const float*)d_in[1];
    const float* Wout = (const float*)d_in[2];
    float* out = (float*)d_out;

    __half *x16, *wq16, *wo16, *q16, *k16, *v16, *att16;
    cudaGetSymbolAddress((void**)&x16, g_x16);
    cudaGetSymbolAddress((void**)&wq16, g_wqkvT);
    cudaGetSymbolAddress((void**)&wo16, g_woutT);
    cudaGetSymbolAddress((void**)&q16, g_q16);
    cudaGetSymbolAddress((void**)&k16, g_k16);
    cudaGetSymbolAddress((void**)&v16, g_v16);
    cudaGetSymbolAddress((void**)&att16, g_att16);

    cudaFuncSetAttribute((const void*)gemm_mma_kernel<0>,
                         cudaFuncAttributeMaxDynamicSharedMemorySize, GEMM_SMEM);
    cudaFuncSetAttribute((const void*)gemm_mma_kernel<1>,
                         cudaFuncAttributeMaxDynamicSharedMemorySize, GEMM_SMEM);
    cudaFuncSetAttribute((const void*)attn_mma_kernel,
                         cudaFuncAttributeMaxDynamicSharedMemorySize, ATT_SMEM);

    // merged prep: convert x + transpose both weights, single launch
    prep_kernel<<<NCONV + NTQ + NTO, 256>>>(x, Wqkv, Wout, x16, wq16, wo16);

    // 1) qkv GEMM (persistent) -> fp16 head-major q/k/v (q pre-scaled)
    gemm_mma_kernel<1><<<PERSIST_CTAS, 256, GEMM_SMEM>>>(
        x16, wq16, nullptr, q16, k16, v16, TOKENS, 3 * DMODEL, DMODEL);

    // 2) tensor-core causal flash attention -> att fp16
    attn_mma_kernel<<<dim3(LSEQ / 128, BH_CNT), 256, ATT_SMEM>>>(
        q16, k16, v16, att16);

    // 3) out = att @ Wout (persistent)
    gemm_mma_kernel<0><<<PERSIST_CTAS, 256, GEMM_SMEM>>>(
        att16, wo16, out, nullptr, nullptr, nullptr, TOKENS, DMODEL, DMODEL);
}